// round 4
// baseline (speedup 1.0000x reference)
#include <cuda_runtime.h>

#define NF 32
#define RPB 16          // rows per block
#define THREADS 256     // 8 warps; phase1: 16 thr/row; phase2: 2 rows/warp

// -----------------------------------------------------------------------------
// out[b,2d] = (1/32) sum_f sin(x[b,f] w_d), out[b,2d+1] = (1/32) sum_f cos(...)
// w_d = 10^(-d/64). Taylor-separable:
//   sin_mean = w * Horner_v(A),  cos_mean = Horner_v(B),  v = w^2 = 10^(-d/32)
//   A_j = S_{2j+1}(-1)^j/((2j+1)! 32),  B_j = S_{2j}(-1)^j/((2j)! 32), B_0 = 1
// Lane handles d = 2*lane, 2*lane+1; iteration advances d by 64: v *= 0.01.
// -----------------------------------------------------------------------------

#define C32 0.9305720409297f   /* 10^(-1/32) */
#define C64 0.9646616199111f   /* 10^(-1/64) */

template<int JS, int JC>
__device__ __forceinline__ float4 eval_pair(const float* A, const float* B,
                                            float va, float vb,
                                            float wa, float wb)
{
    float hsa = A[JS - 1], hsb = A[JS - 1];
#pragma unroll
    for (int j = JS - 2; j >= 0; --j) {
        hsa = fmaf(va, hsa, A[j]);
        hsb = fmaf(vb, hsb, A[j]);
    }
    float hca = B[JC - 1], hcb = B[JC - 1];
#pragma unroll
    for (int j = JC - 2; j >= 0; --j) {
        hca = fmaf(va, hca, B[j]);
        hcb = fmaf(vb, hcb, B[j]);
    }
    return make_float4(wa * hsa, hca, wb * hsb, hcb);
}

__global__ void __launch_bounds__(THREADS)
pe_fused_kernel(const float* __restrict__ x, float4* __restrict__ out)
{
    __shared__ __align__(16) float scoef[RPB][24];   // A[0..11], B[1..12]

    const int tid  = threadIdx.x;
    const int row0 = blockIdx.x * RPB;

    // ---------------- Phase 1: power sums, 16 threads per row ----------------
    {
        const int rg  = tid >> 4;    // row in block 0..15
        const int sub = tid & 15;    // covers f = 2*sub, 2*sub+1

        float2 xv = *(const float2*)(x + (row0 + rg) * NF + sub * 2);

        float So[12], Se[12];
#pragma unroll
        for (int j = 0; j < 12; ++j) { So[j] = 0.f; Se[j] = 0.f; }

        float xs2[2] = {xv.x, xv.y};
#pragma unroll
        for (int k = 0; k < 2; ++k) {
            float xx = xs2[k];
            float x2 = xx * xx;
            float p = xx, q = x2;
            So[0] += p; Se[0] += q;
#pragma unroll
            for (int j = 1; j < 12; ++j) {
                p *= x2; q *= x2;
                So[j] += p; Se[j] += q;
            }
        }

        // butterfly reduce within the 16-thread group (stays inside half-warp)
#pragma unroll
        for (int off = 1; off < 16; off <<= 1) {
#pragma unroll
            for (int j = 0; j < 12; ++j) {
                So[j] += __shfl_xor_sync(0xffffffffu, So[j], off);
                Se[j] += __shfl_xor_sync(0xffffffffu, Se[j], off);
            }
        }

        if (sub == 0) {
            const float ka[12] = {
                (float)( 1.0 / 32.0),
                (float)(-1.0 / (6.0 * 32.0)),
                (float)( 1.0 / (120.0 * 32.0)),
                (float)(-1.0 / (5040.0 * 32.0)),
                (float)( 1.0 / (362880.0 * 32.0)),
                (float)(-1.0 / (39916800.0 * 32.0)),
                (float)( 1.0 / (6227020800.0 * 32.0)),
                (float)(-1.0 / (1307674368000.0 * 32.0)),
                (float)( 1.0 / (355687428096000.0 * 32.0)),
                (float)(-1.0 / (121645100408832000.0 * 32.0)),
                (float)( 1.0 / (51090942171709440000.0 * 32.0)),
                (float)(-1.0 / (25852016738884976640000.0 * 32.0))
            };
            const float kb[12] = {
                (float)(-1.0 / (2.0 * 32.0)),
                (float)( 1.0 / (24.0 * 32.0)),
                (float)(-1.0 / (720.0 * 32.0)),
                (float)( 1.0 / (40320.0 * 32.0)),
                (float)(-1.0 / (3628800.0 * 32.0)),
                (float)( 1.0 / (479001600.0 * 32.0)),
                (float)(-1.0 / (87178291200.0 * 32.0)),
                (float)( 1.0 / (20922789888000.0 * 32.0)),
                (float)(-1.0 / (6402373705728000.0 * 32.0)),
                (float)( 1.0 / (2432902008176640000.0 * 32.0)),
                (float)(-1.0 / (1124000727777607680000.0 * 32.0)),
                (float)( 1.0 / (620448401733239439360000.0 * 32.0))
            };
            float4* cf = (float4*)scoef[rg];
            cf[0] = make_float4(So[0]*ka[0], So[1]*ka[1], So[2]*ka[2],  So[3]*ka[3]);
            cf[1] = make_float4(So[4]*ka[4], So[5]*ka[5], So[6]*ka[6],  So[7]*ka[7]);
            cf[2] = make_float4(So[8]*ka[8], So[9]*ka[9], So[10]*ka[10],So[11]*ka[11]);
            cf[3] = make_float4(Se[0]*kb[0], Se[1]*kb[1], Se[2]*kb[2],  Se[3]*kb[3]);
            cf[4] = make_float4(Se[4]*kb[4], Se[5]*kb[5], Se[6]*kb[6],  Se[7]*kb[7]);
            cf[5] = make_float4(Se[8]*kb[8], Se[9]*kb[9], Se[10]*kb[10],Se[11]*kb[11]);
        }
    }
    __syncthreads();

    // ---------------- Phase 2: warp-per-row Horner, 2 rows per warp ----------
    {
        const int wrp  = tid >> 5;    // 0..7
        const int lane = tid & 31;

        // lane covers d = 2*lane, 2*lane+1 (iter 0), stepping d += 64 per iter
        // va = 10^(-2l/32), wa = 10^(-2l/64); b = a * 10^(-1/32 or 64)
        const float va0 = exp2f((float)lane * -0.20762050593046014f);
        const float wa0 = exp2f((float)lane * -0.10381025296523007f);
        const float vb0 = va0 * C32;
        const float wb0 = wa0 * C64;

#pragma unroll
        for (int k = 0; k < 2; ++k) {               // 2 rows per warp
            const int rg = wrp * 2 + k;
            const float4* cf = (const float4*)scoef[rg];   // LDS broadcast
            float4 c0 = cf[0], c1 = cf[1], c2 = cf[2];
            float4 c3 = cf[3], c4 = cf[4], c5 = cf[5];

            float A[12] = {c0.x, c0.y, c0.z, c0.w, c1.x, c1.y, c1.z, c1.w,
                           c2.x, c2.y, c2.z, c2.w};
            float B[13] = {1.0f, c3.x, c3.y, c3.z, c3.w, c4.x, c4.y, c4.z, c4.w,
                           c5.x, c5.y, c5.z, c5.w};

            float va = va0, vb = vb0, wa = wa0, wb = wb0;
            // float4 index: row*128 + lane + 32*iter
            float4* o = out + (row0 + rg) * 128 + lane;

            o[0]  = eval_pair<12, 13>(A, B, va, vb, wa, wb);   // d [  0, 64)
            va *= 0.01f; vb *= 0.01f; wa *= 0.1f; wb *= 0.1f;
            o[32] = eval_pair< 4,  4>(A, B, va, vb, wa, wb);   // d [ 64,128) |t|<=0.58
            va *= 0.01f; vb *= 0.01f; wa *= 0.1f; wb *= 0.1f;
            o[64] = eval_pair< 2,  2>(A, B, va, vb, wa, wb);   // d [128,192) |t|<=0.058
            va *= 0.01f; vb *= 0.01f; wa *= 0.1f; wb *= 0.1f;
            o[96] = eval_pair< 1,  2>(A, B, va, vb, wa, wb);   // d [192,256) |t|<=0.0058
        }
    }
}

extern "C" void kernel_launch(void* const* d_in, const int* in_sizes, int n_in,
                              void* d_out, int out_size)
{
    const float* x = (const float*)d_in[0];
    float4* out = (float4*)d_out;
    int rows = in_sizes[0] / NF;                 // 16384
    pe_fused_kernel<<<rows / RPB, THREADS>>>(x, out);
}

// round 5
// speedup vs baseline: 1.2000x; 1.2000x over previous
#include <cuda_runtime.h>

#define NF 32
#define RPB 16           // rows per block
#define THREADS 128      // 4 warps; each warp owns 4 rows end-to-end

// -----------------------------------------------------------------------------
// out[b,2d]   = (1/32) sum_f sin(x[b,f] w_d)
// out[b,2d+1] = (1/32) sum_f cos(x[b,f] w_d),  w_d = 10^(-d/64)
// Taylor-separable: sin_mean = w * Horner_v(A), cos_mean = Horner_v(B),
//   v = w^2 = 10^(-d/32)
//   A_j = S_{2j+1}(-1)^j/((2j+1)! 32)  (ids 0..11)
//   B_j = S_{2j}  (-1)^j/((2j)! 32)    (ids 12..23), B_0 = 1 constant
// Lane covers d = 2*lane, 2*lane+1; step advances d by 64 (v*=0.01, w*=0.1).
// -----------------------------------------------------------------------------

#define C32 0.9305720409297f    /* 10^(-1/32) */
#define C64 0.9646616199111f    /* 10^(-1/64) */

__constant__ float KSCALE[24] = {
    // ka[j] = (-1)^j / ((2j+1)! * 32)
    (float)( 1.0 / 32.0),
    (float)(-1.0 / (6.0 * 32.0)),
    (float)( 1.0 / (120.0 * 32.0)),
    (float)(-1.0 / (5040.0 * 32.0)),
    (float)( 1.0 / (362880.0 * 32.0)),
    (float)(-1.0 / (39916800.0 * 32.0)),
    (float)( 1.0 / (6227020800.0 * 32.0)),
    (float)(-1.0 / (1307674368000.0 * 32.0)),
    (float)( 1.0 / (355687428096000.0 * 32.0)),
    (float)(-1.0 / (121645100408832000.0 * 32.0)),
    (float)( 1.0 / (51090942171709440000.0 * 32.0)),
    (float)(-1.0 / (25852016738884976640000.0 * 32.0)),
    // kb[j] = (-1)^(j+1) / ((2j+2)! * 32)   (for S_2 .. S_24)
    (float)(-1.0 / (2.0 * 32.0)),
    (float)( 1.0 / (24.0 * 32.0)),
    (float)(-1.0 / (720.0 * 32.0)),
    (float)( 1.0 / (40320.0 * 32.0)),
    (float)(-1.0 / (3628800.0 * 32.0)),
    (float)( 1.0 / (479001600.0 * 32.0)),
    (float)(-1.0 / (87178291200.0 * 32.0)),
    (float)( 1.0 / (20922789888000.0 * 32.0)),
    (float)(-1.0 / (6402373705728000.0 * 32.0)),
    (float)( 1.0 / (2432902008176640000.0 * 32.0)),
    (float)(-1.0 / (1124000727777607680000.0 * 32.0)),
    (float)( 1.0 / (620448401733239439360000.0 * 32.0))
};

template<int JS, int JC>
__device__ __forceinline__ float4 eval_pair(const float* A, const float* B,
                                            float va, float vb,
                                            float wa, float wb)
{
    float hsa = A[JS - 1], hsb = A[JS - 1];
#pragma unroll
    for (int j = JS - 2; j >= 0; --j) {
        hsa = fmaf(va, hsa, A[j]);
        hsb = fmaf(vb, hsb, A[j]);
    }
    float hca = B[JC - 1], hcb = B[JC - 1];
#pragma unroll
    for (int j = JC - 2; j >= 0; --j) {
        hca = fmaf(va, hca, B[j]);
        hcb = fmaf(vb, hcb, B[j]);
    }
    return make_float4(wa * hsa, hca, wb * hsb, hcb);
}

__global__ void __launch_bounds__(THREADS)
pe_kernel(const float* __restrict__ x, float4* __restrict__ out)
{
    __shared__ __align__(16) float scoef[RPB][24];

    const int tid  = threadIdx.x;
    const int wrp  = tid >> 5;
    const int lane = tid & 31;
    const int row0 = blockIdx.x * RPB;

    // ======== Phase 1: power sums, 8 threads/row (warp covers its 4 rows) ====
    {
        const int rg  = tid >> 3;    // row in block 0..15 (= wrp*4 + lane>>3)
        const int sub = lane & 7;

        // coalesced: warp reads 4 rows x 128B = 512B contiguous
        float4 xv = *(const float4*)(x + (row0 + rg) * NF + sub * 4);

        // val[0..11] = S_1,S_3,..,S_23 ; val[12..23] = S_2,S_4,..,S_24
        float val[24];
#pragma unroll
        for (int i = 0; i < 24; ++i) val[i] = 0.f;

        float xs4[4] = {xv.x, xv.y, xv.z, xv.w};
#pragma unroll
        for (int k = 0; k < 4; ++k) {
            float xx = xs4[k];
            float x2 = xx * xx;
            val[0] += xx;            // S_1
            float q = x2;
            val[12] += q;            // S_2
#pragma unroll
            for (int j = 1; j < 12; ++j) {
                val[j] = fmaf(xx, q, val[j]);   // S_{2j+1} = x * x2^j
                q *= x2;
                val[12 + j] += q;               // S_{2j+2}
            }
        }

        // ---- reduce-scatter across the 8-thread group: 12+6+3 = 21 shfls ----
        {   // round 1: 24 -> 12, partner ^1
            const bool hi = (sub & 1);
#pragma unroll
            for (int i = 0; i < 12; ++i) {
                float keep = hi ? val[i + 12] : val[i];
                float send = hi ? val[i]      : val[i + 12];
                val[i] = keep + __shfl_xor_sync(0xffffffffu, send, 1);
            }
        }
        {   // round 2: 12 -> 6, partner ^2
            const bool hi = (sub >> 1) & 1;
#pragma unroll
            for (int i = 0; i < 6; ++i) {
                float keep = hi ? val[i + 6] : val[i];
                float send = hi ? val[i]     : val[i + 6];
                val[i] = keep + __shfl_xor_sync(0xffffffffu, send, 2);
            }
        }
        {   // round 3: 6 -> 3, partner ^4
            const bool hi = (sub >> 2) & 1;
#pragma unroll
            for (int i = 0; i < 3; ++i) {
                float keep = hi ? val[i + 3] : val[i];
                float send = hi ? val[i]     : val[i + 3];
                val[i] = keep + __shfl_xor_sync(0xffffffffu, send, 4);
            }
        }

        // thread owns ids base..base+2 (fully reduced); scale + store (3 STS)
        const int base = 12 * (sub & 1) + 6 * ((sub >> 1) & 1) + 3 * ((sub >> 2) & 1);
#pragma unroll
        for (int i = 0; i < 3; ++i)
            scoef[rg][base + i] = val[i] * KSCALE[base + i];
    }
    __syncwarp();   // producer lanes == consumer lanes: warp-local handoff

    // ======== Phase 2: warp-per-4-rows Horner evaluation ====================
    {
        // lane covers d = 2*lane, 2*lane+1; w = 10^(-d/64), v = w^2
        const float wa0 = exp2f((float)lane * -0.10381025296523007f); // 10^(-2l/64)
        const float va0 = exp2f((float)lane * -0.20762050593046014f); // 10^(-2l/32)
        const float vb0 = va0 * C32;
        const float wb0 = wa0 * C64;

#pragma unroll
        for (int k = 0; k < 4; ++k) {
            const int rg = wrp * 4 + k;
            const float4* cf = (const float4*)scoef[rg];   // LDS broadcast
            float4 c0 = cf[0], c1 = cf[1], c2 = cf[2];
            float4 c3 = cf[3], c4 = cf[4], c5 = cf[5];

            float A[12] = {c0.x, c0.y, c0.z, c0.w, c1.x, c1.y, c1.z, c1.w,
                           c2.x, c2.y, c2.z, c2.w};
            float B[13] = {1.0f, c3.x, c3.y, c3.z, c3.w, c4.x, c4.y, c4.z, c4.w,
                           c5.x, c5.y, c5.z, c5.w};

            float va = va0, vb = vb0, wa = wa0, wb = wb0;
            float4* o = out + (row0 + rg) * 128 + lane;    // float4 granules

            o[0]  = eval_pair<12, 13>(A, B, va, vb, wa, wb);  // d [  0, 64) |t|<=5.8
            va *= 0.01f; vb *= 0.01f; wa *= 0.1f; wb *= 0.1f;
            o[32] = eval_pair< 4,  4>(A, B, va, vb, wa, wb);  // d [ 64,128) |t|<=0.58
            va *= 0.01f; vb *= 0.01f; wa *= 0.1f; wb *= 0.1f;
            o[64] = eval_pair< 2,  2>(A, B, va, vb, wa, wb);  // d [128,192) |t|<=0.058
            va *= 0.01f; vb *= 0.01f; wa *= 0.1f; wb *= 0.1f;
            o[96] = eval_pair< 1,  2>(A, B, va, vb, wa, wb);  // d [192,256)
        }
    }
}

extern "C" void kernel_launch(void* const* d_in, const int* in_sizes, int n_in,
                              void* d_out, int out_size)
{
    const float* x = (const float*)d_in[0];
    float4* out = (float4*)d_out;
    int rows = in_sizes[0] / NF;                 // 16384
    pe_kernel<<<rows / RPB, THREADS>>>(x, out);
}